// round 12
// baseline (speedup 1.0000x reference)
#include <cuda_runtime.h>
#include <math.h>

#define NB 2
#define NV 120000
#define NT 600000

#define TOTAL_E (NB * NT * 6)       // 7,200,000
#define TOTAL_T (NB * NT)           // 1,200,000
#define TOTAL_V (NB * NV)           //   240,000
#define PTS_FLOATS ((size_t)TOTAL_E * 3)  // 21,600,000

#define MEAN_SUB 32
#define MEAN_BLKS (NB * MEAN_SUB)                      // 64 (first in grid)
#define ZERO_BLKS 1500
#define INIT_BLKS (MEAN_BLKS + ZERO_BLKS)              // 1564
#define TET_BLK 128
#define TET_BLKS (TOTAL_T / TET_BLK)                   // 9375 exact
#define VERT_BLKS ((TOTAL_V + 255) / 256)              // 938

// ---------------- scratch (device globals; no allocations allowed) ----------
__device__ float4   g_term[TOTAL_V];                   // 3.84 MB
__device__ float    g_cnt[TOTAL_V];                    // 0.96 MB
__device__ float4   g_partial4[MEAN_BLKS];             // [batch*32 + sub]
__device__ double   g_acc[3];                          // L1 sumsq, L2 sum, L3 sum
__device__ unsigned g_done;

__device__ __forceinline__ void red_add_v4(float4* addr, float a, float b, float c, float d)
{
    asm volatile("red.global.add.v4.f32 [%0], {%1, %2, %3, %4};"
                 :: "l"(addr), "f"(a), "f"(b), "f"(c), "f"(d) : "memory");
}

// ---------------- K0: mean partials (blocks 0..63) + zero scratch ------------
__global__ void __launch_bounds__(256) k_init(const float4* __restrict__ pred)
{
    int bid = blockIdx.x, tid = threadIdx.x;

    if (bid < MEAN_BLKS) {
        // mean partials first: start in wave 1, overlap with zeroing
        int b = bid / MEAN_SUB, sub = bid % MEAN_SUB;
        float sx = 0.f, sy = 0.f, sz = 0.f, sw = 0.f;
        #pragma unroll 4
        for (int i = sub * 256 + tid; i < NV; i += MEAN_SUB * 256) {
            float4 v = pred[b * NV + i];
            sx += v.x; sy += v.y; sz += v.z; sw += v.w;
        }
        #pragma unroll
        for (int o = 16; o; o >>= 1) {
            sx += __shfl_down_sync(0xFFFFFFFFu, sx, o);
            sy += __shfl_down_sync(0xFFFFFFFFu, sy, o);
            sz += __shfl_down_sync(0xFFFFFFFFu, sz, o);
            sw += __shfl_down_sync(0xFFFFFFFFu, sw, o);
        }
        __shared__ float sh[8][4];
        if ((tid & 31) == 0) {
            int w = tid >> 5;
            sh[w][0] = sx; sh[w][1] = sy; sh[w][2] = sz; sh[w][3] = sw;
        }
        __syncthreads();
        if (tid == 0) {
            float ax = 0.f, ay = 0.f, az = 0.f, aw = 0.f;
            #pragma unroll
            for (int i = 0; i < 8; i++) { ax += sh[i][0]; ay += sh[i][1]; az += sh[i][2]; aw += sh[i][3]; }
            g_partial4[b * MEAN_SUB + sub] = make_float4(ax, ay, az, aw);
        }
        return;
    }

    // zero g_term (240000 float4) + g_cnt (60000 float4) = 300000 float4
    int zb = bid - MEAN_BLKS;
    float4 z = make_float4(0.f, 0.f, 0.f, 0.f);
    float4* c4 = reinterpret_cast<float4*>(g_cnt);
    for (int i = zb * 256 + tid; i < 300000; i += ZERO_BLKS * 256) {
        if (i < TOTAL_V) g_term[i] = z;
        else             c4[i - TOTAL_V] = z;
    }
    if (zb == 0) {
        if (tid < 3) g_acc[tid] = 0.0;
        if (tid == 4) g_done = 0u;
    }
}

// ---------------- K1: fused per-tet kernel (R8-proven body + tweaks) ---------
__global__ void __launch_bounds__(TET_BLK) k_tet(
    const float4* __restrict__ pred, const int4* __restrict__ tetra,
    float* __restrict__ out)
{
    __shared__ __align__(16) float s_pts[TET_BLK * 18];   // 9 KB
    __shared__ __align__(16) float s_msk[TET_BLK * 6];    // 3 KB
    __shared__ float s_mean[8];
    __shared__ float s2[4], s3[4];

    int tid = threadIdx.x;
    int lane = tid & 31;
    int wrp = tid >> 5;
    int gid = blockIdx.x * TET_BLK + tid;   // always < TOTAL_T (exact tiling)

    // warps 0-1: reduce 32 float4 partials each via shuffles (64 LDG.128/block)
    if (tid < 64) {
        float4 pv = g_partial4[wrp * MEAN_SUB + lane];
        #pragma unroll
        for (int o = 16; o; o >>= 1) {
            pv.x += __shfl_down_sync(0xFFFFFFFFu, pv.x, o);
            pv.y += __shfl_down_sync(0xFFFFFFFFu, pv.y, o);
            pv.z += __shfl_down_sync(0xFFFFFFFFu, pv.z, o);
            pv.w += __shfl_down_sync(0xFFFFFFFFu, pv.w, o);
        }
        if (lane == 0) {
            const float inv = 1.f / (float)NV;
            s_mean[wrp * 4 + 0] = pv.x * inv;
            s_mean[wrp * 4 + 1] = pv.y * inv;
            s_mean[wrp * 4 + 2] = pv.z * inv;
            s_mean[wrp * 4 + 3] = pv.w * inv;
        }
    }

    int b = (gid >= NT) ? 1 : 0;
    int4 f = __ldcs(&tetra[gid]);           // streaming read-once
    const float4* p = pred + (size_t)b * NV;
    float4 v[4];
    v[0] = p[f.x]; v[1] = p[f.y]; v[2] = p[f.z]; v[3] = p[f.w];

    float sx = v[0].x + v[1].x + v[2].x + v[3].x;
    float sy = v[0].y + v[1].y + v[2].y + v[3].y;
    float sz = v[0].z + v[1].z + v[2].z + v[3].z;
    float sw = v[0].w + v[1].w + v[2].w + v[3].w;

    // ---- Laplacian scatter (mean cancels in vsum - 4v) ----
    {
        int base = b * NV;
        int vi[4] = {f.x, f.y, f.z, f.w};
        #pragma unroll
        for (int k = 0; k < 4; k++) {
            red_add_v4(&g_term[base + vi[k]],
                       sx - 4.f * v[k].x, sy - 4.f * v[k].y,
                       sz - 4.f * v[k].z, sw - 4.f * v[k].w);
            atomicAdd(&g_cnt[base + vi[k]], 1.f);
        }
    }

    __syncthreads();   // s_mean ready

    float l2sum = 0.f, l3sum = 0.f;
    {
        float mx = s_mean[b * 4 + 0];
        float my = s_mean[b * 4 + 1];
        float mz = s_mean[b * 4 + 2];
        float mw = s_mean[b * 4 + 3];

        const int EA[6] = {0, 0, 0, 1, 1, 2};
        const int EB[6] = {1, 2, 3, 2, 3, 3};
        #pragma unroll
        for (int e = 0; e < 6; e++) {
            float4 va = v[EA[e]];
            float4 vb = v[EB[e]];
            float wa = va.w - mw;
            float wb = vb.w - mw;
            float prod = wa * wb;           // ALPHA = 0
            l2sum += prod;

            float dx = va.x - vb.x;         // mean cancels in diffs
            float dy = va.y - vb.y;
            float dz = va.z - vb.z;
            float dw = va.w - vb.w;
            float nrm = sqrtf(dx * dx + dy * dy + dz * dz + dw * dw);
            float l3 = nrm - 0.4f;
            l3sum += l3 * l3;

            float safe_q = (fabsf(dw) > 1e-12f) ? dw : 1.0f;
            float t = -wa / safe_q;

            bool m = prod < 0.f;
            float px = 0.f, py = 0.f, pz = 0.f;
            if (m) {
                px = (va.x - mx) + t * dx;
                py = (va.y - my) + t * dy;
                pz = (va.z - mz) + t * dz;
            }
            s_pts[tid * 18 + e * 3 + 0] = px;
            s_pts[tid * 18 + e * 3 + 1] = py;
            s_pts[tid * 18 + e * 3 + 2] = pz;
            s_msk[tid * 6 + e] = m ? 1.f : 0.f;
        }
    }

    // ---- reduce L2 / L3 within warp ----
    #pragma unroll
    for (int o = 16; o; o >>= 1) {
        l2sum += __shfl_down_sync(0xFFFFFFFFu, l2sum, o);
        l3sum += __shfl_down_sync(0xFFFFFFFFu, l3sum, o);
    }
    if (lane == 0) { s2[wrp] = l2sum; s3[wrp] = l3sum; }

    // ---- warp-local writeout: each warp reads back only what it staged ------
    __syncwarp();
    const float4* sp4 = reinterpret_cast<const float4*>(s_pts);
    const float4* sm4 = reinterpret_cast<const float4*>(s_msk);

    float4* op = reinterpret_cast<float4*>(out + 4 + (size_t)blockIdx.x * (TET_BLK * 18));
    int pbase = wrp * 144;                  // 32 tets * 18 floats / 4
    #pragma unroll
    for (int r = 0; r < 4; r++)
        __stcs(&op[pbase + r * 32 + lane], sp4[pbase + r * 32 + lane]);
    if (lane < 16)
        __stcs(&op[pbase + 128 + lane], sp4[pbase + 128 + lane]);

    float4* om = reinterpret_cast<float4*>(out + 4 + PTS_FLOATS + (size_t)blockIdx.x * (TET_BLK * 6));
    int mbase = wrp * 48;                   // 32 tets * 6 floats / 4
    __stcs(&om[mbase + lane], sm4[mbase + lane]);
    if (lane < 16)
        __stcs(&om[mbase + 32 + lane], sm4[mbase + 32 + lane]);

    __syncthreads();                        // s2/s3 visibility for tid 0
    if (tid == 0) {
        float a2 = 0.f, a3 = 0.f;
        #pragma unroll
        for (int i = 0; i < 4; i++) { a2 += s2[i]; a3 += s3[i]; }
        atomicAdd(&g_acc[1], (double)a2);
        atomicAdd(&g_acc[2], (double)a3);
    }
}

// ---------------- K2: per-vertex L1 finalize + loss writeout -----------------
__global__ void __launch_bounds__(256) k_vert_final(float* __restrict__ out)
{
    int gid = blockIdx.x * 256 + threadIdx.x;
    float s = 0.f;
    if (gid < TOTAL_V) {
        float4 t = g_term[gid];
        float c = g_cnt[gid];
        float inv = 1.f / fmaxf(3.f * c, 1.f);
        float ax = t.x * inv, ay = t.y * inv, az = t.z * inv, aw = t.w * inv;
        s = ax * ax + ay * ay + az * az + aw * aw;
    }
    #pragma unroll
    for (int o = 16; o; o >>= 1) s += __shfl_down_sync(0xFFFFFFFFu, s, o);
    __shared__ float sh[8];
    if ((threadIdx.x & 31) == 0) sh[threadIdx.x >> 5] = s;
    __syncthreads();
    if (threadIdx.x == 0) {
        float a = 0.f;
        #pragma unroll
        for (int i = 0; i < 8; i++) a += sh[i];
        atomicAdd(&g_acc[0], (double)a);
        __threadfence();
        unsigned old = atomicInc(&g_done, 0xFFFFFFFFu);
        if (old == VERT_BLKS - 1) {
            out[0] = (float)(g_acc[0] / (double)((size_t)NB * NV * 4));
            out[1] = (float)(g_acc[1] / (double)TOTAL_E);
            out[2] = (float)(g_acc[2] / (double)TOTAL_E);
            out[3] = 0.f;
        }
    }
}

// ---------------- launch ------------------------------------------------------
extern "C" void kernel_launch(void* const* d_in, const int* in_sizes, int n_in,
                              void* d_out, int out_size)
{
    const float4* pred  = (const float4*)d_in[0];   // (B, N, 4) fp32
    const int4*   tetra = (const int4*)d_in[1];     // (B, T, 4) int32
    float* out = (float*)d_out;

    k_init<<<INIT_BLKS, 256>>>(pred);
    k_tet<<<TET_BLKS, TET_BLK>>>(pred, tetra, out);
    k_vert_final<<<VERT_BLKS, 256>>>(out);
}

// round 13
// speedup vs baseline: 1.4928x; 1.4928x over previous
#include <cuda_runtime.h>
#include <math.h>

#define NB 2
#define NV 120000
#define NT 600000

#define TOTAL_E (NB * NT * 6)       // 7,200,000
#define TOTAL_T (NB * NT)           // 1,200,000
#define TOTAL_V (NB * NV)           //   240,000
#define PTS_FLOATS ((size_t)TOTAL_E * 3)  // 21,600,000

#define MEAN_SUB 60
#define MEAN_BLKS (NB * MEAN_SUB)                      // 120 (first in grid)
#define ZERO_BLKS 1500
#define INIT_BLKS (MEAN_BLKS + ZERO_BLKS)              // 1620
#define TET_BLK 128
#define TET_BLKS (TOTAL_T / TET_BLK)                   // 9375 exact
#define VERT_BLKS ((TOTAL_V + 255) / 256)              // 938

// ---------------- scratch (device globals; no allocations allowed) ----------
__device__ float4   g_term[TOTAL_V];                   // 3.84 MB
__device__ float    g_cnt[TOTAL_V];                    // 0.96 MB
__device__ float    g_partial[NB * MEAN_SUB * 4];      // mean partials (overwritten)
__device__ double   g_acc[3];                          // L1 sumsq, L2 sum, L3 sum
__device__ unsigned g_done;

__device__ __forceinline__ void red_add_v4(float4* addr, float a, float b, float c, float d)
{
    asm volatile("red.global.add.v4.f32 [%0], {%1, %2, %3, %4};"
                 :: "l"(addr), "f"(a), "f"(b), "f"(c), "f"(d) : "memory");
}

// ---------------- K0: mean partials (blocks 0..119) + zero scratch -----------
__global__ void __launch_bounds__(256) k_init(const float4* __restrict__ pred)
{
    int bid = blockIdx.x, tid = threadIdx.x;

    if (bid < MEAN_BLKS) {
        // mean partials first: start in wave 1, overlap with zeroing
        int b = bid / MEAN_SUB, sub = bid % MEAN_SUB;
        float sx = 0.f, sy = 0.f, sz = 0.f, sw = 0.f;
        for (int i = sub * 256 + tid; i < NV; i += MEAN_SUB * 256) {
            float4 v = pred[b * NV + i];
            sx += v.x; sy += v.y; sz += v.z; sw += v.w;
        }
        #pragma unroll
        for (int o = 16; o; o >>= 1) {
            sx += __shfl_down_sync(0xFFFFFFFFu, sx, o);
            sy += __shfl_down_sync(0xFFFFFFFFu, sy, o);
            sz += __shfl_down_sync(0xFFFFFFFFu, sz, o);
            sw += __shfl_down_sync(0xFFFFFFFFu, sw, o);
        }
        __shared__ float sh[8][4];
        if ((tid & 31) == 0) {
            int w = tid >> 5;
            sh[w][0] = sx; sh[w][1] = sy; sh[w][2] = sz; sh[w][3] = sw;
        }
        __syncthreads();
        if (tid == 0) {
            float ax = 0.f, ay = 0.f, az = 0.f, aw = 0.f;
            #pragma unroll
            for (int i = 0; i < 8; i++) { ax += sh[i][0]; ay += sh[i][1]; az += sh[i][2]; aw += sh[i][3]; }
            float* p = &g_partial[(b * MEAN_SUB + sub) * 4];
            p[0] = ax; p[1] = ay; p[2] = az; p[3] = aw;
        }
        return;
    }

    // zero g_term (240000 float4) + g_cnt (60000 float4) = 300000 float4
    int zb = bid - MEAN_BLKS;
    float4 z = make_float4(0.f, 0.f, 0.f, 0.f);
    float4* c4 = reinterpret_cast<float4*>(g_cnt);
    for (int i = zb * 256 + tid; i < 300000; i += ZERO_BLKS * 256) {
        if (i < TOTAL_V) g_term[i] = z;
        else             c4[i - TOTAL_V] = z;
    }
    if (zb == 0) {
        if (tid < 3) g_acc[tid] = 0.0;
        if (tid == 4) g_done = 0u;
    }
}

// ---------------- K1: fused per-tet kernel (exact R8 body, occ-capped) -------
__global__ void __launch_bounds__(TET_BLK, 12) k_tet(
    const float4* __restrict__ pred, const int4* __restrict__ tetra,
    float* __restrict__ out)
{
    __shared__ __align__(16) float s_pts[TET_BLK * 18];   // 9 KB
    __shared__ __align__(16) float s_msk[TET_BLK * 6];    // 3 KB
    __shared__ float s_mean[8];
    __shared__ float s2[4], s3[4];

    int tid = threadIdx.x;
    int gid = blockIdx.x * TET_BLK + tid;   // always < TOTAL_T (exact tiling)

    if (tid < 8) {
        int b = tid >> 2, c = tid & 3;
        float s = 0.f;
        #pragma unroll
        for (int k = 0; k < MEAN_SUB; k++) s += g_partial[(b * MEAN_SUB + k) * 4 + c];
        s_mean[tid] = s * (1.f / (float)NV);
    }

    int b = (gid >= NT) ? 1 : 0;
    int4 f = __ldcs(&tetra[gid]);           // streaming read-once
    const float4* p = pred + (size_t)b * NV;
    float4 v[4];
    v[0] = p[f.x]; v[1] = p[f.y]; v[2] = p[f.z]; v[3] = p[f.w];

    float sx = v[0].x + v[1].x + v[2].x + v[3].x;
    float sy = v[0].y + v[1].y + v[2].y + v[3].y;
    float sz = v[0].z + v[1].z + v[2].z + v[3].z;
    float sw = v[0].w + v[1].w + v[2].w + v[3].w;

    // ---- Laplacian scatter (mean cancels in vsum - 4v) ----
    {
        int base = b * NV;
        int vi[4] = {f.x, f.y, f.z, f.w};
        #pragma unroll
        for (int k = 0; k < 4; k++) {
            red_add_v4(&g_term[base + vi[k]],
                       sx - 4.f * v[k].x, sy - 4.f * v[k].y,
                       sz - 4.f * v[k].z, sw - 4.f * v[k].w);
            atomicAdd(&g_cnt[base + vi[k]], 1.f);
        }
    }

    __syncthreads();   // s_mean ready

    float l2sum = 0.f, l3sum = 0.f;
    {
        float mx = s_mean[b * 4 + 0];
        float my = s_mean[b * 4 + 1];
        float mz = s_mean[b * 4 + 2];
        float mw = s_mean[b * 4 + 3];

        const int EA[6] = {0, 0, 0, 1, 1, 2};
        const int EB[6] = {1, 2, 3, 2, 3, 3};
        #pragma unroll
        for (int e = 0; e < 6; e++) {
            float4 va = v[EA[e]];
            float4 vb = v[EB[e]];
            float wa = va.w - mw;
            float wb = vb.w - mw;
            float prod = wa * wb;           // ALPHA = 0
            l2sum += prod;

            float dx = va.x - vb.x;         // mean cancels in diffs
            float dy = va.y - vb.y;
            float dz = va.z - vb.z;
            float dw = va.w - vb.w;
            float nrm = sqrtf(dx * dx + dy * dy + dz * dz + dw * dw);
            float l3 = nrm - 0.4f;
            l3sum += l3 * l3;

            float safe_q = (fabsf(dw) > 1e-12f) ? dw : 1.0f;
            float t = -wa / safe_q;

            bool m = prod < 0.f;
            float px = 0.f, py = 0.f, pz = 0.f;
            if (m) {
                px = (va.x - mx) + t * dx;
                py = (va.y - my) + t * dy;
                pz = (va.z - mz) + t * dz;
            }
            s_pts[tid * 18 + e * 3 + 0] = px;
            s_pts[tid * 18 + e * 3 + 1] = py;
            s_pts[tid * 18 + e * 3 + 2] = pz;
            s_msk[tid * 6 + e] = m ? 1.f : 0.f;
        }
    }

    // ---- block reduce L2 / L3 ----
    #pragma unroll
    for (int o = 16; o; o >>= 1) {
        l2sum += __shfl_down_sync(0xFFFFFFFFu, l2sum, o);
        l3sum += __shfl_down_sync(0xFFFFFFFFu, l3sum, o);
    }
    if ((tid & 31) == 0) { s2[tid >> 5] = l2sum; s3[tid >> 5] = l3sum; }
    __syncthreads();

    // ---- coalesced vectorized streaming writeout (bases 16B aligned) ----
    const float4* sp4 = reinterpret_cast<const float4*>(s_pts);
    const float4* sm4 = reinterpret_cast<const float4*>(s_msk);

    float4* op = reinterpret_cast<float4*>(out + 4 + (size_t)blockIdx.x * (TET_BLK * 18));
    #pragma unroll
    for (int r = 0; r < (TET_BLK * 18 / 4) / TET_BLK; r++)        // 4 full rounds
        __stcs(&op[r * TET_BLK + tid], sp4[r * TET_BLK + tid]);
    {
        int i = (TET_BLK * 18 / 4) / TET_BLK * TET_BLK + tid;     // tail 64
        if (i < TET_BLK * 18 / 4) __stcs(&op[i], sp4[i]);
    }

    float4* om = reinterpret_cast<float4*>(out + 4 + PTS_FLOATS + (size_t)blockIdx.x * (TET_BLK * 6));
    {
        int i = tid;                                              // 192 = 128 + 64
        __stcs(&om[i], sm4[i]);
        i += TET_BLK;
        if (i < TET_BLK * 6 / 4) __stcs(&om[i], sm4[i]);
    }

    if (tid == 0) {
        float a2 = 0.f, a3 = 0.f;
        #pragma unroll
        for (int i = 0; i < 4; i++) { a2 += s2[i]; a3 += s3[i]; }
        atomicAdd(&g_acc[1], (double)a2);
        atomicAdd(&g_acc[2], (double)a3);
    }
}

// ---------------- K2: per-vertex L1 finalize + loss writeout -----------------
__global__ void __launch_bounds__(256) k_vert_final(float* __restrict__ out)
{
    int gid = blockIdx.x * 256 + threadIdx.x;
    float s = 0.f;
    if (gid < TOTAL_V) {
        float4 t = g_term[gid];
        float c = g_cnt[gid];
        float inv = 1.f / fmaxf(3.f * c, 1.f);
        float ax = t.x * inv, ay = t.y * inv, az = t.z * inv, aw = t.w * inv;
        s = ax * ax + ay * ay + az * az + aw * aw;
    }
    #pragma unroll
    for (int o = 16; o; o >>= 1) s += __shfl_down_sync(0xFFFFFFFFu, s, o);
    __shared__ float sh[8];
    if ((threadIdx.x & 31) == 0) sh[threadIdx.x >> 5] = s;
    __syncthreads();
    if (threadIdx.x == 0) {
        float a = 0.f;
        #pragma unroll
        for (int i = 0; i < 8; i++) a += sh[i];
        atomicAdd(&g_acc[0], (double)a);
        __threadfence();
        unsigned old = atomicInc(&g_done, 0xFFFFFFFFu);
        if (old == VERT_BLKS - 1) {
            out[0] = (float)(g_acc[0] / (double)((size_t)NB * NV * 4));
            out[1] = (float)(g_acc[1] / (double)TOTAL_E);
            out[2] = (float)(g_acc[2] / (double)TOTAL_E);
            out[3] = 0.f;
        }
    }
}

// ---------------- launch ------------------------------------------------------
extern "C" void kernel_launch(void* const* d_in, const int* in_sizes, int n_in,
                              void* d_out, int out_size)
{
    const float4* pred  = (const float4*)d_in[0];   // (B, N, 4) fp32
    const int4*   tetra = (const int4*)d_in[1];     // (B, T, 4) int32
    float* out = (float*)d_out;

    k_init<<<INIT_BLKS, 256>>>(pred);
    k_tet<<<TET_BLKS, TET_BLK>>>(pred, tetra, out);
    k_vert_final<<<VERT_BLKS, 256>>>(out);
}